// round 7
// baseline (speedup 1.0000x reference)
#include <cuda_runtime.h>
#include <math.h>

#define BB 2
#define HH 8
#define SS 1024
#define DD 64
#define PP 8
#define DK 128        // 2*D
#define RR 16
#define NPOS (BB*HH*SS)   // 16384
#define EPSF 1e-6f

// ---------------- device scratch (no allocation allowed) ----------------
__device__ __align__(16) float g_W0f[PP*DK*DD];  // softplus(w0)^2 * sigmoid(g0), [p][k][d]
__device__ __align__(16) float g_Mf [PP*DK*DD];  // sigmoid(g1)*softplus(w1[p,d,k])^2 + zw[p,k,d], [p][k][d]
__device__ float g_b0f[PP*DK];
__device__ float g_cf [PP*DD];
__device__ float g_obb[PP];
__device__ float g_tau[NPOS];
__device__ __align__(16) float g_phiq[NPOS*RR];
__device__ __align__(16) float g_phik[NPOS*RR];
__device__ float g_gk [NPOS];
__device__ __align__(16) float g_wh[(size_t)BB*SS*HH*SS];  // [b][i][h][j] normalized w, 64MB
__device__ float g_aacc[BB*SS];

__device__ __forceinline__ float sp_acc(float x){ return fmaxf(x,0.f) + log1pf(expf(-fabsf(x))); }
__device__ __forceinline__ float spf(float x){ return fmaxf(x,0.f) + __logf(1.f + __expf(-fabsf(x))); }
__device__ __forceinline__ float sigm(float x){ return 1.f/(1.f+expf(-x)); }

// ---------------- fold k-hull weights ----------------
__global__ void prep_weights(const float* __restrict__ w0, const float* __restrict__ b0,
                             const float* __restrict__ w1, const float* __restrict__ b1,
                             const float* __restrict__ zw, const float* __restrict__ g0,
                             const float* __restrict__ g1, const float* __restrict__ ob){
    int e = blockIdx.x*blockDim.x + threadIdx.x;
    if (e >= PP*DK*DD) return;
    int p = e >> 13;             // /(128*64)
    int kd = e & 8191;
    int k = kd >> 6;
    int d = kd & 63;
    float s0 = sigm(g0[p]), s1 = sigm(g1[p]);
    float a = sp_acc(w0[e]);
    g_W0f[e] = a*a*s0;                             // fold g0 into W0
    float wv = w1[(p*DD + d)*DK + k];              // w1[p,d,k]
    float bsp = sp_acc(wv);
    g_Mf[e] = s1*bsp*bsp + zw[e];                  // M[p,k,d]
    if (e < PP*DK) g_b0f[e] = b0[e]*sigm(g0[e>>7]);
    if (e < PP*DD) g_cf[e]  = sigm(g1[e>>6])*b1[e];
    if (e < PP){
        float s = 0.f;
        for (int dd=0; dd<DD; dd++) s += ob[e*DD+dd];
        g_obb[e] = s*(1.f/DD);
    }
}

__global__ void zero_a(){
    int e = blockIdx.x*blockDim.x + threadIdx.x;
    if (e < BB*SS) g_aacc[e] = 0.f;
}

// ---------------- per-position prep: tau (q) + phi (q gated / k raw) ----------------
template<bool ISQ>
__global__ void qk_prep(const float* __restrict__ x, const float* __restrict__ wh){
    __shared__ float Wsh[RR*DD];
    int t = threadIdx.x;
    for (int i=t;i<RR*DD;i+=256) Wsh[i]=wh[i];
    __syncthreads();
    int w = t>>5, lane = t&31;
    int n = blockIdx.x*8 + w;
    float x0 = x[(size_t)n*DD + lane];
    float x1 = x[(size_t)n*DD + 32 + lane];
    if (ISQ){ x0 *= spf(x0); x1 *= spf(x1); }     // q = q*softplus(q)
    float ss = x0*x0 + x1*x1;
    #pragma unroll
    for (int o=16;o;o>>=1) ss += __shfl_xor_sync(0xffffffffu, ss, o);
    if (ISQ && lane==0)
        g_tau[n] = __expf(0.30343f*sqrtf(ss*(1.f/DD)+EPSF)+0.22159f);
    #pragma unroll
    for (int r=0;r<RR;r++){
        float dv = x0*Wsh[r*DD+lane] + x1*Wsh[r*DD+32+lane];
        #pragma unroll
        for (int o=16;o;o>>=1) dv += __shfl_xor_sync(0xffffffffu, dv, o);
        if (lane == r){
            float ph = spf(fminf(dv, 20.f)) + EPSF;  // store phi+EPS
            if (ISQ) g_phiq[(size_t)n*RR + r] = ph;
            else     g_phik[(size_t)n*RR + r] = ph;
        }
    }
}

// ---------------- k-side scalar hull (ICNN), 64 positions / block ----------------
__global__ void khull(const float* __restrict__ kin, const float* __restrict__ gw,
                      const float* __restrict__ gb){
    extern __shared__ float sm[];
    float* Xs  = sm;               // [64 d][65]  xg tile, d-major
    float* Ws  = Xs  + 64*65;      // [128][65]   W0 then M
    float* Z0s = Ws  + 128*65;     // [128][65]
    float* Ssc = Z0s + 128*65;     // [64][8]
    float* tsh = Ssc + 512;        // [64]
    float* gsh = tsh + 64;
    float* gwsh= gsh + 64;
    int t = threadIdx.x;
    int pos0 = blockIdx.x*64;
    if (t < 64) gwsh[t] = gw[t];
    for (int e=t;e<64*64;e+=256){
        int pos=e>>6, d=e&63;
        Xs[d*65+pos] = kin[(size_t)(pos0+pos)*DD + d];
    }
    for (int e=t;e<512;e+=256) Ssc[e]=0.f;
    __syncthreads();
    if (t < 64){
        float dot=0.f, ssq=0.f;
        for (int d=0;d<64;d++){ float xv=Xs[d*65+t]; dot += xv*gwsh[d]; ssq += xv*xv; }
        float u = spf(dot + gb[0]);
        float g = 1.f - __expf(-u);                  // convex gate
        gsh[t]=g;
        ssq *= g*g;                                  // rms of xg = k*g
        tsh[t] = __expf(0.30343f*sqrtf(ssq*(1.f/64)+EPSF)+0.22159f);
    }
    __syncthreads();
    for (int e=t;e<64*64;e+=256){
        int pos=e>>6, d=e&63;
        Xs[d*65+pos] *= gsh[pos];
    }
    __syncthreads();
    int pg = t & 15, kg = t >> 4;
    for (int p=0;p<PP;p++){
        { // load W0[p] -> Ws
            const float4* src = (const float4*)(g_W0f + p*8192);
            for (int i=t;i<2048;i+=256){
                float4 vv = src[i];
                int kk = i>>4, d0 = (i&15)*4;
                float* dst = Ws + kk*65 + d0;
                dst[0]=vv.x; dst[1]=vv.y; dst[2]=vv.z; dst[3]=vv.w;
            }
        }
        __syncthreads();
        // GEMM1: z0[k][pos] = softplus(xg . W0f + b0f), tile 4pos x 8k / thread
        float acc[4][8];
        #pragma unroll
        for (int i=0;i<4;i++)
            #pragma unroll
            for (int j=0;j<8;j++) acc[i][j]=0.f;
        for (int d=0;d<64;d++){
            float xv[4];
            #pragma unroll
            for (int i=0;i<4;i++) xv[i]=Xs[d*65 + pg*4 + i];
            #pragma unroll
            for (int j=0;j<8;j++){
                float wv = Ws[(kg*8+j)*65 + d];
                #pragma unroll
                for (int i=0;i<4;i++) acc[i][j] += xv[i]*wv;
            }
        }
        #pragma unroll
        for (int j=0;j<8;j++){
            int kq = kg*8+j;
            float bb = g_b0f[p*DK+kq];
            #pragma unroll
            for (int i=0;i<4;i++)
                Z0s[kq*65 + pg*4+i] = spf(acc[i][j] + bb);
        }
        __syncthreads();
        { // load M[p] -> Ws
            const float4* src = (const float4*)(g_Mf + p*8192);
            for (int i=t;i<2048;i+=256){
                float4 vv = src[i];
                int kk = i>>4, d0 = (i&15)*4;
                float* dst = Ws + kk*65 + d0;
                dst[0]=vv.x; dst[1]=vv.y; dst[2]=vv.z; dst[3]=vv.w;
            }
        }
        __syncthreads();
        // GEMM2: z1[pos][d] = softplus(z0 . M + c); Ssc[pos][p] += sum_d
        float acc2[4][4];
        #pragma unroll
        for (int i=0;i<4;i++)
            #pragma unroll
            for (int j=0;j<4;j++) acc2[i][j]=0.f;
        for (int kq=0;kq<128;kq++){
            float zv[4];
            #pragma unroll
            for (int i=0;i<4;i++) zv[i]=Z0s[kq*65 + pg*4+i];
            #pragma unroll
            for (int j=0;j<4;j++){
                float mv = Ws[kq*65 + kg*4+j];
                #pragma unroll
                for (int i=0;i<4;i++) acc2[i][j] += zv[i]*mv;
            }
        }
        #pragma unroll
        for (int i=0;i<4;i++){
            float part=0.f;
            #pragma unroll
            for (int j=0;j<4;j++)
                part += spf(acc2[i][j] + g_cf[p*DD + kg*4+j]);
            atomicAdd(&Ssc[(pg*4+i)*8 + p], part);
        }
        __syncthreads();
    }
    if (t < 64){
        float th = tsh[t];
        float l[PP], m=-1e30f;
        #pragma unroll
        for (int p=0;p<PP;p++){
            l[p] = (Ssc[t*8+p]*(1.f/64) + g_obb[p])*th;
            m = fmaxf(m, l[p]);
        }
        float s=0.f;
        #pragma unroll
        for (int p=0;p<PP;p++) s += __expf(l[p]-m);
        g_gk[pos0+t] = (m + __logf(s))/th;
    }
}

// ---------------- attention: 8 query rows per block ----------------
__global__ void attn(const float* __restrict__ v, const float* __restrict__ mask,
                     float* __restrict__ outp){
    extern __shared__ float sm[];
    float* E   = sm;                 // [8][1024]  (unnormalized exp weights)
    float* Rd  = E + 8*1024;         // [8 warps][8 rows][64 d] partial outs
    float* Pq  = Rd + 8*8*64;        // [8][16]
    int t = threadIdx.x, w = t>>5, lane = t&31;
    int bh = blockIdx.y;
    int b = bh>>3, h = bh&7;
    int i0 = blockIdx.x*8;
    if (t < 128) Pq[t] = g_phiq[(size_t)(bh*1024 + i0 + (t>>4))*RR + (t&15)];
    __syncthreads();
    int i = i0 + w;
    size_t n = (size_t)bh*1024 + i;
    float ti = g_tau[n];
    float pq[16];
    #pragma unroll
    for (int r=0;r<16;r++) pq[r]=Pq[w*16+r];
    const float* mrow = mask + n*1024;
    const float* pkb  = g_phik + (size_t)bh*1024*RR;
    const float* gkb  = g_gk + bh*1024;
    float m = -1e30f;
    for (int j=lane; j<1024; j+=32){
        const float4* pk = (const float4*)(pkb + j*16);
        float4 a0=pk[0], a1=pk[1], a2=pk[2], a3=pk[3];
        float dot = pq[0]*a0.x + pq[1]*a0.y + pq[2]*a0.z + pq[3]*a0.w
                  + pq[4]*a1.x + pq[5]*a1.y + pq[6]*a1.z + pq[7]*a1.w
                  + pq[8]*a2.x + pq[9]*a2.y + pq[10]*a2.z + pq[11]*a2.w
                  + pq[12]*a3.x + pq[13]*a3.y + pq[14]*a3.z + pq[15]*a3.w;
        // log(dot)+log(mask) == log(dot*mask) (one extra fp32 rounding)
        float l = ti*(gkb[j] + __logf(dot*fmaxf(mrow[j], EPSF)));
        E[w*1024+j] = l;
        m = fmaxf(m, l);
    }
    #pragma unroll
    for (int o=16;o;o>>=1) m = fmaxf(m, __shfl_xor_sync(0xffffffffu, m, o));
    float z = 0.f;
    for (int j=lane;j<1024;j+=32){
        float e = __expf(E[w*1024+j]-m);
        E[w*1024+j]=e; z+=e;
    }
    #pragma unroll
    for (int o=16;o;o>>=1) z += __shfl_xor_sync(0xffffffffu, z, o);
    float inv = 1.f/z;                 // E stays unnormalized in smem
    // stream normalized row w[b,h,i,:] to g_wh[b][i][h][:]  (for the a-path)
    float* wrow = g_wh + (((size_t)b*SS + i)*HH + h)*SS;
    for (int j0=lane*4; j0<1024; j0+=128){
        float4 e4 = *(float4*)&E[w*1024+j0];
        e4.x*=inv; e4.y*=inv; e4.z*=inv; e4.w*=inv;
        *(float4*)&wrow[j0] = e4;
    }
    __syncthreads();
    // Phase 2: partial w@v. Warp w: j in [128w, 128w+128); lane holds d=2lane,2lane+1.
    float2 po[8];
    #pragma unroll
    for (int r=0;r<8;r++) po[r] = make_float2(0.f,0.f);
    const float2* vb2 = (const float2*)(v + (size_t)bh*1024*64);
    int jbeg = w*128;
    #pragma unroll 4
    for (int j0=jbeg; j0<jbeg+128; j0+=2){
        float2 e[8];
        #pragma unroll
        for (int r=0;r<8;r++) e[r] = *(const float2*)&E[r*1024+j0];
        float2 v0 = vb2[(size_t)j0*32 + lane];
        float2 v1 = vb2[(size_t)(j0+1)*32 + lane];
        #pragma unroll
        for (int r=0;r<8;r++){
            po[r].x += e[r].x*v0.x + e[r].y*v1.x;
            po[r].y += e[r].x*v0.y + e[r].y*v1.y;
        }
    }
    #pragma unroll
    for (int r=0;r<8;r++)
        *(float2*)&Rd[(w*8+r)*64 + 2*lane] = po[r];
    __syncthreads();
    // warp w reduces its own row i=w across the 8 j-partials
    float s0=0.f, s1=0.f;
    #pragma unroll
    for (int ww=0;ww<8;ww++){
        s0 += Rd[(ww*8+w)*64 + lane];
        s1 += Rd[(ww*8+w)*64 + 32+lane];
    }
    outp[n*64+lane]    = s0*inv;
    outp[n*64+32+lane] = s1*inv;
}

// ---------------- block reduction helper ----------------
__device__ __forceinline__ float blkred(float v, int op){
    __shared__ float red[32];
    __shared__ float res;
    int lane = threadIdx.x&31, wid = threadIdx.x>>5;
    int nw = (blockDim.x+31)>>5;
    #pragma unroll
    for (int o=16;o;o>>=1){
        float tt = __shfl_xor_sync(0xffffffffu, v, o);
        v = (op==0)? v+tt : (op==1)? fmaxf(v,tt) : fminf(v,tt);
    }
    __syncthreads();
    if (lane==0) red[wid]=v;
    __syncthreads();
    if (wid==0){
        float x = (lane<nw)? red[lane] : ((op==0)?0.f:(op==1)?-1e30f:1e30f);
        #pragma unroll
        for (int o=16;o;o>>=1){
            float tt = __shfl_xor_sync(0xffffffffu, x, o);
            x = (op==0)? x+tt : (op==1)? fmaxf(x,tt) : fminf(x,tt);
        }
        if (lane==0) res = x;
    }
    __syncthreads();
    return res;
}

// ---------------- a-path: A[b,i,j]=sum_h w; softmax_j; accumulate mean_i ----------------
// block = (b, 8-row i-chunk); 256 threads, thread owns 4 consecutive j.
__global__ void asum(){
    int blk = blockIdx.x;
    int b = blk >> 7;            // /128
    int i0 = (blk & 127)*8;
    int t = threadIdx.x;
    int jb = t*4;
    float acc[4] = {0.f,0.f,0.f,0.f};
    for (int ii=0; ii<8; ii++){
        const float* base = g_wh + (((size_t)b*SS + i0+ii)*HH)*SS;
        float A[4] = {0.f,0.f,0.f,0.f};
        #pragma unroll
        for (int h=0;h<HH;h++){
            float4 vv = *(const float4*)&base[(size_t)h*SS + jb];
            A[0]+=vv.x; A[1]+=vv.y; A[2]+=vv.z; A[3]+=vv.w;
        }
        float m = fmaxf(fmaxf(A[0],A[1]),fmaxf(A[2],A[3]));
        m = blkred(m,1);
        float e[4]; float ls=0.f;
        #pragma unroll
        for (int u=0;u<4;u++){ e[u]=__expf(A[u]-m); ls+=e[u]; }
        float s = blkred(ls,0);
        float invs = 1.f/s;
        #pragma unroll
        for (int u=0;u<4;u++) acc[u] += e[u]*invs;
    }
    #pragma unroll
    for (int u=0;u<4;u++) atomicAdd(&g_aacc[b*SS + jb+u], acc[u]);
}

// ---------------- final: a = minmax(acc/S) ----------------
__global__ void finalb(float* __restrict__ aout){
    int b = blockIdx.x, j = threadIdx.x;
    float a = g_aacc[b*SS+j]*(1.f/SS);
    float mn = blkred(a, 2);
    float mx = blkred(a, 1);
    aout[b*SS + j] = (a - mn)/(mx - mn + EPSF);
}

extern "C" void kernel_launch(void* const* d_in, const int* in_sizes, int n_in,
                              void* d_out, int out_size) {
    const float* q    = (const float*)d_in[0];
    const float* k    = (const float*)d_in[1];
    const float* v    = (const float*)d_in[2];
    const float* mask = (const float*)d_in[3];
    const float *whq, *whk;
    int kb;  // index of k_w0
    if (in_sizes[4] == RR*DD){            // layout: q,k,v,mask,whq,whk,q_params,k_params
        whq = (const float*)d_in[4];
        whk = (const float*)d_in[5];
        kb = 16;
    } else {                              // layout: q,k,v,mask,q_params,k_params,whq,whk
        kb = 14;
        whq = (const float*)d_in[24];
        whk = (const float*)d_in[25];
    }
    const float* k_w0 = (const float*)d_in[kb+0];
    const float* k_b0 = (const float*)d_in[kb+1];
    const float* k_w1 = (const float*)d_in[kb+2];
    const float* k_b1 = (const float*)d_in[kb+3];
    const float* k_zw = (const float*)d_in[kb+4];
    const float* k_g0 = (const float*)d_in[kb+5];
    const float* k_g1 = (const float*)d_in[kb+6];
    const float* k_ob = (const float*)d_in[kb+7];
    const float* k_gw = (const float*)d_in[kb+8];
    const float* k_gb = (const float*)d_in[kb+9];

    float* outp = (float*)d_out;
    float* aout = outp + (size_t)BB*HH*SS*DD;

    cudaFuncSetAttribute(khull, cudaFuncAttributeMaxDynamicSharedMemorySize, 86016);
    cudaFuncSetAttribute(attn,  cudaFuncAttributeMaxDynamicSharedMemorySize, 50176);

    prep_weights<<<256,256>>>(k_w0,k_b0,k_w1,k_b1,k_zw,k_g0,k_g1,k_ob);
    zero_a<<<8,256>>>();
    qk_prep<true ><<<NPOS/8,256>>>(q, whq);
    qk_prep<false><<<NPOS/8,256>>>(k, whk);
    khull<<<NPOS/64,256,86016>>>(k, k_gw, k_gb);
    attn<<<dim3(SS/8, BB*HH),256,50176>>>(v, mask, outp);
    asum<<<BB*SS/8,256>>>();
    finalb<<<BB,SS>>>(aout);
}

// round 11
// speedup vs baseline: 1.2226x; 1.2226x over previous
#include <cuda_runtime.h>
#include <math.h>

#define BB 2
#define HH 8
#define SS 1024
#define DD 64
#define PP 8
#define DK 128        // 2*D
#define RR 16
#define NPOS (BB*HH*SS)   // 16384
#define EPSF 1e-6f

// ---------------- device scratch (no allocation allowed) ----------------
__device__ __align__(16) float g_W0t[PP*DD*DK];  // softplus(w0)^2*sigmoid(g0), TRANSPOSED [p][d][k]
__device__ __align__(16) float g_Mf [PP*DK*DD];  // sigmoid(g1)*softplus(w1[p,d,k])^2 + zw[p,k,d], [p][k][d]
__device__ float g_b0f[PP*DK];
__device__ float g_cf [PP*DD];
__device__ float g_obb[PP];
__device__ float g_tau[NPOS];
__device__ __align__(16) float g_phiq[NPOS*RR];
__device__ __align__(16) float g_phik[NPOS*RR];
__device__ float g_gk [NPOS];
__device__ __align__(16) float g_wh[(size_t)BB*SS*HH*SS];  // [b][i][h][j] normalized w, 64MB
__device__ float g_aacc[BB*SS];

__device__ __forceinline__ float sp_acc(float x){ return fmaxf(x,0.f) + log1pf(expf(-fabsf(x))); }
__device__ __forceinline__ float spf(float x){ return fmaxf(x,0.f) + __logf(1.f + __expf(-fabsf(x))); }
__device__ __forceinline__ float sigm(float x){ return 1.f/(1.f+expf(-x)); }

// ---------------- fold k-hull weights ----------------
__global__ void prep_weights(const float* __restrict__ w0, const float* __restrict__ b0,
                             const float* __restrict__ w1, const float* __restrict__ b1,
                             const float* __restrict__ zw, const float* __restrict__ g0,
                             const float* __restrict__ g1, const float* __restrict__ ob){
    int e = blockIdx.x*blockDim.x + threadIdx.x;
    if (e >= PP*DK*DD) return;
    int p = e >> 13;             // /(128*64)
    int kd = e & 8191;
    int k = kd >> 6;
    int d = kd & 63;
    float s0 = sigm(g0[p]), s1 = sigm(g1[p]);
    float a = sp_acc(w0[e]);
    g_W0t[(p*DD + d)*DK + k] = a*a*s0;             // fold g0, transpose to [p][d][k]
    float wv = w1[(p*DD + d)*DK + k];              // w1[p,d,k]
    float bsp = sp_acc(wv);
    g_Mf[e] = s1*bsp*bsp + zw[e];                  // M[p,k,d]
    if (e < PP*DK) g_b0f[e] = b0[e]*sigm(g0[e>>7]);
    if (e < PP*DD) g_cf[e]  = sigm(g1[e>>6])*b1[e];
    if (e < PP){
        float s = 0.f;
        for (int dd=0; dd<DD; dd++) s += ob[e*DD+dd];
        g_obb[e] = s*(1.f/DD);
    }
}

__global__ void zero_a(){
    int e = blockIdx.x*blockDim.x + threadIdx.x;
    if (e < BB*SS) g_aacc[e] = 0.f;
}

// ---------------- per-position prep: tau (q) + phi (q gated / k raw) ----------------
template<bool ISQ>
__global__ void qk_prep(const float* __restrict__ x, const float* __restrict__ wh){
    __shared__ float Wsh[RR*DD];
    int t = threadIdx.x;
    for (int i=t;i<RR*DD;i+=256) Wsh[i]=wh[i];
    __syncthreads();
    int w = t>>5, lane = t&31;
    int n = blockIdx.x*8 + w;
    float x0 = x[(size_t)n*DD + lane];
    float x1 = x[(size_t)n*DD + 32 + lane];
    if (ISQ){ x0 *= spf(x0); x1 *= spf(x1); }     // q = q*softplus(q)
    float ss = x0*x0 + x1*x1;
    #pragma unroll
    for (int o=16;o;o>>=1) ss += __shfl_xor_sync(0xffffffffu, ss, o);
    if (ISQ && lane==0)
        g_tau[n] = __expf(0.30343f*sqrtf(ss*(1.f/DD)+EPSF)+0.22159f);
    #pragma unroll
    for (int r=0;r<RR;r++){
        float dv = x0*Wsh[r*DD+lane] + x1*Wsh[r*DD+32+lane];
        #pragma unroll
        for (int o=16;o;o>>=1) dv += __shfl_xor_sync(0xffffffffu, dv, o);
        if (lane == r){
            float ph = spf(fminf(dv, 20.f)) + EPSF;  // store phi+EPS
            if (ISQ) g_phiq[(size_t)n*RR + r] = ph;
            else     g_phik[(size_t)n*RR + r] = ph;
        }
    }
}

// ---------------- k-side scalar hull (ICNN), 64 positions / block ----------------
// float4 LDS everywhere: GEMM1 = 3 LDS.128 + 32 FFMA per d-iter,
// GEMM2 = 2 LDS.128 + 16 FFMA per k-iter.
#define XST 68    // Xs/Z0s/M row stride (floats, mult of 4)
#define WST 132   // W0t row stride (floats, mult of 4)
__global__ void khull(const float* __restrict__ kin, const float* __restrict__ gw,
                      const float* __restrict__ gb){
    extern __shared__ float sm[];
    float* Xs  = sm;                 // [64 d][XST]  xg tile, d-major
    float* Ws  = Xs  + 64*XST;       // GEMM1: [64 d][WST] W0t ; GEMM2: [128 k][XST] M
    float* Z0s = Ws  + 128*XST;      // [128 k][XST]   (128*XST >= 64*WST: 8704 >= 8448)
    float* Ssc = Z0s + 128*XST;      // [64][8]
    float* tsh = Ssc + 512;          // [64]
    float* gsh = tsh + 64;
    float* gwsh= gsh + 64;
    int t = threadIdx.x;
    int pos0 = blockIdx.x*64;
    if (t < 64) gwsh[t] = gw[t];
    for (int e=t;e<64*64;e+=256){
        int pos=e>>6, d=e&63;
        Xs[d*XST+pos] = kin[(size_t)(pos0+pos)*DD + d];
    }
    for (int e=t;e<512;e+=256) Ssc[e]=0.f;
    __syncthreads();
    if (t < 64){
        float dot=0.f, ssq=0.f;
        for (int d=0;d<64;d++){ float xv=Xs[d*XST+t]; dot += xv*gwsh[d]; ssq += xv*xv; }
        float u = spf(dot + gb[0]);
        float g = 1.f - __expf(-u);                  // convex gate
        gsh[t]=g;
        ssq *= g*g;                                  // rms of xg = k*g
        tsh[t] = __expf(0.30343f*sqrtf(ssq*(1.f/64)+EPSF)+0.22159f);
    }
    __syncthreads();
    for (int e=t;e<64*64;e+=256){
        int pos=e>>6, d=e&63;
        Xs[d*XST+pos] *= gsh[pos];
    }
    __syncthreads();
    int pg = t & 15, kg = t >> 4;
    for (int p=0;p<PP;p++){
        { // load W0t[p] ([64][128]) -> Ws rows stride WST
            const float4* src = (const float4*)(g_W0t + p*8192);
            for (int i=t;i<2048;i+=256){
                float4 vv = src[i];
                int d = i>>5, k4 = (i&31)*4;
                *(float4*)&Ws[d*WST + k4] = vv;
            }
        }
        __syncthreads();
        // GEMM1: z0[k][pos] = softplus(xg . W0 + b0f), tile 4pos x 8k / thread
        float acc[4][8];
        #pragma unroll
        for (int i=0;i<4;i++)
            #pragma unroll
            for (int j=0;j<8;j++) acc[i][j]=0.f;
        for (int d=0;d<64;d++){
            float4 x4 = *(const float4*)&Xs[d*XST + pg*4];
            float4 wa = *(const float4*)&Ws[d*WST + kg*8];
            float4 wb = *(const float4*)&Ws[d*WST + kg*8 + 4];
            float xv[4] = {x4.x,x4.y,x4.z,x4.w};
            float wv[8] = {wa.x,wa.y,wa.z,wa.w, wb.x,wb.y,wb.z,wb.w};
            #pragma unroll
            for (int j=0;j<8;j++)
                #pragma unroll
                for (int i=0;i<4;i++) acc[i][j] += xv[i]*wv[j];
        }
        #pragma unroll
        for (int j=0;j<8;j++){
            int kq = kg*8+j;
            float bb = g_b0f[p*DK+kq];
            float4 o;
            o.x = spf(acc[0][j]+bb); o.y = spf(acc[1][j]+bb);
            o.z = spf(acc[2][j]+bb); o.w = spf(acc[3][j]+bb);
            *(float4*)&Z0s[kq*XST + pg*4] = o;
        }
        __syncthreads();
        { // load M[p] ([128][64]) -> Ws rows stride XST
            const float4* src = (const float4*)(g_Mf + p*8192);
            for (int i=t;i<2048;i+=256){
                float4 vv = src[i];
                int k = i>>4, d4 = (i&15)*4;
                *(float4*)&Ws[k*XST + d4] = vv;
            }
        }
        __syncthreads();
        // GEMM2: z1[pos][d] = softplus(z0 . M + c); Ssc[pos][p] += sum_d
        float acc2[4][4];
        #pragma unroll
        for (int i=0;i<4;i++)
            #pragma unroll
            for (int j=0;j<4;j++) acc2[i][j]=0.f;
        for (int kq=0;kq<128;kq++){
            float4 z4 = *(const float4*)&Z0s[kq*XST + pg*4];
            float4 m4 = *(const float4*)&Ws[kq*XST + kg*4];
            float zv[4] = {z4.x,z4.y,z4.z,z4.w};
            float mv[4] = {m4.x,m4.y,m4.z,m4.w};
            #pragma unroll
            for (int j=0;j<4;j++)
                #pragma unroll
                for (int i=0;i<4;i++) acc2[i][j] += zv[i]*mv[j];
        }
        #pragma unroll
        for (int i=0;i<4;i++){
            float part=0.f;
            #pragma unroll
            for (int j=0;j<4;j++)
                part += spf(acc2[i][j] + g_cf[p*DD + kg*4+j]);
            atomicAdd(&Ssc[(pg*4+i)*8 + p], part);
        }
        __syncthreads();
    }
    if (t < 64){
        float th = tsh[t];
        float l[PP], m=-1e30f;
        #pragma unroll
        for (int p=0;p<PP;p++){
            l[p] = (Ssc[t*8+p]*(1.f/64) + g_obb[p])*th;
            m = fmaxf(m, l[p]);
        }
        float s=0.f;
        #pragma unroll
        for (int p=0;p<PP;p++) s += __expf(l[p]-m);
        g_gk[pos0+t] = (m + __logf(s))/th;
    }
}

// ---------------- attention: 8 query rows per block ----------------
// Phase 1: phik staged in smem chunks (256 j x 16 r, stride 20 -> conflict-free
// LDS.128) shared by all 8 warps: 8x less L2 phik traffic.
// Phase 2: j-split w@v with register partials; Rd overlays the PK buffer.
#define PKST 20
__global__ void attn(const float* __restrict__ v, const float* __restrict__ mask,
                     float* __restrict__ outp){
    extern __shared__ float sm[];
    float* E   = sm;                 // [8][1024]  (unnormalized exp weights)
    float* PK  = E + 8*1024;         // [256 j][PKST]  phase-1 phik chunk (5120 floats)
    float* Rd  = PK;                 // overlay: [8 warps][8 rows][64 d] phase-2 partials (4096)
    float* Pq  = PK + 256*PKST;      // [8][16]
    int t = threadIdx.x, w = t>>5, lane = t&31;
    int bh = blockIdx.y;
    int b = bh>>3, h = bh&7;
    int i0 = blockIdx.x*8;
    if (t < 128) Pq[t] = g_phiq[(size_t)(bh*1024 + i0 + (t>>4))*RR + (t&15)];
    __syncthreads();
    int i = i0 + w;
    size_t n = (size_t)bh*1024 + i;
    float ti = g_tau[n];
    float pq[16];
    #pragma unroll
    for (int r=0;r<16;r++) pq[r]=Pq[w*16+r];
    const float* mrow = mask + n*1024;
    const float* pkb  = g_phik + (size_t)bh*1024*RR;
    const float* gkb  = g_gk + bh*1024;
    float m = -1e30f;
    for (int c=0;c<4;c++){
        __syncthreads();   // previous chunk fully consumed before overwrite
        { // cooperative load: 256 j x 16 r -> PK rows (stride PKST)
            const float4* src = (const float4*)(pkb + (size_t)c*256*RR);
            for (int q=t;q<1024;q+=256){
                float4 vv = src[q];
                int j = q>>2, r4 = (q&3)*4;
                *(float4*)&PK[j*PKST + r4] = vv;
            }
        }
        __syncthreads();
        for (int j=lane; j<256; j+=32){
            int jg = c*256 + j;
            const float4* pk = (const float4*)&PK[j*PKST];
            float4 a0=pk[0], a1=pk[1], a2=pk[2], a3=pk[3];
            float dot = pq[0]*a0.x + pq[1]*a0.y + pq[2]*a0.z + pq[3]*a0.w
                      + pq[4]*a1.x + pq[5]*a1.y + pq[6]*a1.z + pq[7]*a1.w
                      + pq[8]*a2.x + pq[9]*a2.y + pq[10]*a2.z + pq[11]*a2.w
                      + pq[12]*a3.x + pq[13]*a3.y + pq[14]*a3.z + pq[15]*a3.w;
            // log(dot)+log(mask) == log(dot*mask) (one extra fp32 rounding)
            float l = ti*(gkb[jg] + __logf(dot*fmaxf(mrow[jg], EPSF)));
            E[w*1024+jg] = l;
            m = fmaxf(m, l);
        }
    }
    #pragma unroll
    for (int o=16;o;o>>=1) m = fmaxf(m, __shfl_xor_sync(0xffffffffu, m, o));
    float z = 0.f;
    for (int j=lane;j<1024;j+=32){
        float e = __expf(E[w*1024+j]-m);
        E[w*1024+j]=e; z+=e;
    }
    #pragma unroll
    for (int o=16;o;o>>=1) z += __shfl_xor_sync(0xffffffffu, z, o);
    float inv = 1.f/z;                 // E stays unnormalized in smem
    // stream normalized row w[b,h,i,:] to g_wh[b][i][h][:]  (a-path)
    float* wrow = g_wh + (((size_t)b*SS + i)*HH + h)*SS;
    for (int j0=lane*4; j0<1024; j0+=128){
        float4 e4 = *(float4*)&E[w*1024+j0];
        e4.x*=inv; e4.y*=inv; e4.z*=inv; e4.w*=inv;
        *(float4*)&wrow[j0] = e4;
    }
    __syncthreads();   // all PK reads done; Rd overlay now safe
    // Phase 2: partial w@v. Warp w: j in [128w,128w+128); lane holds d=2lane,2lane+1.
    float2 po[8];
    #pragma unroll
    for (int r=0;r<8;r++) po[r] = make_float2(0.f,0.f);
    const float2* vb2 = (const float2*)(v + (size_t)bh*1024*64);
    int jbeg = w*128;
    #pragma unroll 4
    for (int j0=jbeg; j0<jbeg+128; j0+=2){
        float2 e[8];
        #pragma unroll
        for (int r=0;r<8;r++) e[r] = *(const float2*)&E[r*1024+j0];
        float2 v0 = vb2[(size_t)j0*32 + lane];
        float2 v1 = vb2[(size_t)(j0+1)*32 + lane];
        #pragma unroll
        for (int r=0;r<8;r++){
            po[r].x += e[r].x*v0.x + e[r].y*v1.x;
            po[r].y += e[r].x*v0.y + e[r].y*v1.y;
        }
    }
    #pragma unroll
    for (int r=0;r<8;r++)
        *(float2*)&Rd[(w*8+r)*64 + 2*lane] = po[r];
    __syncthreads();
    float s0=0.f, s1=0.f;
    #pragma unroll
    for (int ww=0;ww<8;ww++){
        s0 += Rd[(ww*8+w)*64 + lane];
        s1 += Rd[(ww*8+w)*64 + 32+lane];
    }
    outp[n*64+lane]    = s0*inv;
    outp[n*64+32+lane] = s1*inv;
}

// ---------------- block reduction helper ----------------
__device__ __forceinline__ float blkred(float v, int op){
    __shared__ float red[32];
    __shared__ float res;
    int lane = threadIdx.x&31, wid = threadIdx.x>>5;
    int nw = (blockDim.x+31)>>5;
    #pragma unroll
    for (int o=16;o;o>>=1){
        float tt = __shfl_xor_sync(0xffffffffu, v, o);
        v = (op==0)? v+tt : (op==1)? fmaxf(v,tt) : fminf(v,tt);
    }
    __syncthreads();
    if (lane==0) red[wid]=v;
    __syncthreads();
    if (wid==0){
        float x = (lane<nw)? red[lane] : ((op==0)?0.f:(op==1)?-1e30f:1e30f);
        #pragma unroll
        for (int o=16;o;o>>=1){
            float tt = __shfl_xor_sync(0xffffffffu, x, o);
            x = (op==0)? x+tt : (op==1)? fmaxf(x,tt) : fminf(x,tt);
        }
        if (lane==0) res = x;
    }
    __syncthreads();
    return res;
}

// ---------------- a-path: A[b,i,j]=sum_h w; softmax_j; accumulate mean_i ----------------
__global__ void asum(){
    int blk = blockIdx.x;
    int b = blk >> 7;            // /128
    int i0 = (blk & 127)*8;
    int t = threadIdx.x;
    int jb = t*4;
    float acc[4] = {0.f,0.f,0.f,0.f};
    for (int ii=0; ii<8; ii++){
        const float* base = g_wh + (((size_t)b*SS + i0+ii)*HH)*SS;
        float A[4] = {0.f,0.f,0.f,0.f};
        #pragma unroll
        for (int h=0;h<HH;h++){
            float4 vv = *(const float4*)&base[(size_t)h*SS + jb];
            A[0]+=vv.x; A[1]+=vv.y; A[2]+=vv.z; A[3]+=vv.w;
        }
        float m = fmaxf(fmaxf(A[0],A[1]),fmaxf(A[2],A[3]));
        m = blkred(m,1);
        float e[4]; float ls=0.f;
        #pragma unroll
        for (int u=0;u<4;u++){ e[u]=__expf(A[u]-m); ls+=e[u]; }
        float s = blkred(ls,0);
        float invs = 1.f/s;
        #pragma unroll
        for (int u=0;u<4;u++) acc[u] += e[u]*invs;
    }
    #pragma unroll
    for (int u=0;u<4;u++) atomicAdd(&g_aacc[b*SS + jb+u], acc[u]);
}

// ---------------- final: a = minmax(acc/S) ----------------
__global__ void finalb(float* __restrict__ aout){
    int b = blockIdx.x, j = threadIdx.x;
    float a = g_aacc[b*SS+j]*(1.f/SS);
    float mn = blkred(a, 2);
    float mx = blkred(a, 1);
    aout[b*SS + j] = (a - mn)/(mx - mn + EPSF);
}

extern "C" void kernel_launch(void* const* d_in, const int* in_sizes, int n_in,
                              void* d_out, int out_size) {
    const float* q    = (const float*)d_in[0];
    const float* k    = (const float*)d_in[1];
    const float* v    = (const float*)d_in[2];
    const float* mask = (const float*)d_in[3];
    const float *whq, *whk;
    int kb;  // index of k_w0
    if (in_sizes[4] == RR*DD){            // layout: q,k,v,mask,whq,whk,q_params,k_params
        whq = (const float*)d_in[4];
        whk = (const float*)d_in[5];
        kb = 16;
    } else {                              // layout: q,k,v,mask,q_params,k_params,whq,whk
        kb = 14;
        whq = (const float*)d_in[24];
        whk = (const float*)d_in[25];
    }
    const float* k_w0 = (const float*)d_in[kb+0];
    const float* k_b0 = (const float*)d_in[kb+1];
    const float* k_w1 = (const float*)d_in[kb+2];
    const float* k_b1 = (const float*)d_in[kb+3];
    const float* k_zw = (const float*)d_in[kb+4];
    const float* k_g0 = (const float*)d_in[kb+5];
    const float* k_g1 = (const float*)d_in[kb+6];
    const float* k_ob = (const float*)d_in[kb+7];
    const float* k_gw = (const float*)d_in[kb+8];
    const float* k_gb = (const float*)d_in[kb+9];

    float* outp = (float*)d_out;
    float* aout = outp + (size_t)BB*HH*SS*DD;

    // khull smem: (64*68 + 128*68 + 128*68 + 512 + 192) floats = 89856 B
    cudaFuncSetAttribute(khull, cudaFuncAttributeMaxDynamicSharedMemorySize, 90112);
    // attn smem: (8192 + 5120 + 128) floats = 53760 B
    cudaFuncSetAttribute(attn,  cudaFuncAttributeMaxDynamicSharedMemorySize, 53760);

    prep_weights<<<256,256>>>(k_w0,k_b0,k_w1,k_b1,k_zw,k_g0,k_g1,k_ob);
    zero_a<<<8,256>>>();
    qk_prep<true ><<<NPOS/8,256>>>(q, whq);
    qk_prep<false><<<NPOS/8,256>>>(k, whk);
    khull<<<NPOS/64,256,90112>>>(k, k_gw, k_gb);
    attn<<<dim3(SS/8, BB*HH),256,53760>>>(v, mask, outp);
    asum<<<BB*SS/8,256>>>();
    finalb<<<BB,SS>>>(aout);
}